// round 9
// baseline (speedup 1.0000x reference)
#include <cuda_runtime.h>
#include <math.h>
#include <stdint.h>

#define NB      262144
#define TT      80
#define NSTEP   30
#define RPB     256               // rows (threads) per block / per tile
#define NTILES  (NB / RPB)        // 1024 full tiles
#define TS      34                // tile row stride in floats (8B-aligned cp.async, 2-way LDS)
#define DTC     0.1f
#define GRID    152               // persistent: 1 CTA per SM on GB300
#define NBUF    3                 // triple buffer: 2 tile-loads in flight during compute
#define BUFELEMS (2 * RPB * TS)   // Y + V for one buffer
#define SMEM_BYTES (NBUF * BUFELEMS * sizeof(float))   // 208896 B

__device__ __forceinline__ void cpa8(uint32_t dst, const float* src) {
    asm volatile("cp.async.ca.shared.global [%0], [%1], 8;" :: "r"(dst), "l"(src));
}

__global__ __launch_bounds__(RPB, 1)
void traj_kernel(const float* __restrict__ params,
                 const float* __restrict__ sv_v,
                 const float* __restrict__ hh,
                 const float* __restrict__ dvv,
                 const float* __restrict__ svY,
                 const float* __restrict__ lvY,
                 const float* __restrict__ lvv,
                 float* __restrict__ out)
{
    extern __shared__ float smem[];      // [NBUF][{Y,V}][RPB][TS]
    const int tid   = threadIdx.x;
    const int wid   = tid >> 5;
    const int lane  = tid & 31;
    const int wrow0 = wid * 32;
    const uint32_t smem_u32 = (uint32_t)__cvta_generic_to_shared(smem);

    // Params: broadcast, L1-resident.
    const float s0  = __ldg(params + 0);
    const float Thw = __ldg(params + 1);
    const float pa  = __ldg(params + 2);
    const float pb  = __ldg(params + 3);
    const float v0  = __ldg(params + 4);
    const float inv_c2 = 1.0f / (2.0f * sqrtf(pa * pb));
    const float inv_v0 = 1.0f / v0;

    // Issue this warp's staging loads for tile `tt` into buffer `b`.
    auto stage = [&](int ttile, int b) {
        const int r0 = ttile * RPB;
        const uint32_t ob = (uint32_t)(b * BUFELEMS) * 4u;
        #pragma unroll
        for (int k = 0; k < 16; ++k) {
            int idx = k * 32 + lane;
            int row = wrow0 + (idx >> 4);   // 16 8B-chunks per row
            int c   = idx & 15;
            size_t g = (size_t)(r0 + row) * TT + 48 + c * 2;
            uint32_t dY = smem_u32 + ob + (uint32_t)(row * TS + c * 2) * 4u;
            cpa8(dY, lvY + g);
            cpa8(dY + (uint32_t)(RPB * TS) * 4u, lvv + g);
        }
    };

    int t   = blockIdx.x;
    int buf = 0;

    float c0v = 0.f, c0g = 0.f, c0d = 0.f, c0y = 0.f;   // scalars for tile t
    float c1v = 0.f, c1g = 0.f, c1d = 0.f, c1y = 0.f;   // scalars for tile t+G

    // ---- Prologue: two tiles in flight before first compute. ----
    {
        stage(t, 0);
        asm volatile("cp.async.commit_group;");
        size_t sb = (size_t)(t * RPB + tid) * TT + 49;
        c0v = __ldg(sv_v + sb); c0g = __ldg(hh + sb);
        c0d = __ldg(dvv  + sb); c0y = __ldg(svY + sb);

        int t1 = t + (int)gridDim.x;
        if (t1 < NTILES) {
            stage(t1, 1);
            size_t sb1 = (size_t)(t1 * RPB + tid) * TT + 49;
            c1v = __ldg(sv_v + sb1); c1g = __ldg(hh + sb1);
            c1d = __ldg(dvv  + sb1); c1y = __ldg(svY + sb1);
        }
        asm volatile("cp.async.commit_group;");
    }

    while (t < NTILES) {
        // ---- Issue tile t+2G into buffer (buf+2)%3; commit unconditionally. ----
        const int tn2 = t + 2 * (int)gridDim.x;
        float c2v = 0.f, c2g = 0.f, c2d = 0.f, c2y = 0.f;
        if (tn2 < NTILES) {
            stage(tn2, (buf + 2) % NBUF);
            size_t sb2 = (size_t)(tn2 * RPB + tid) * TT + 49;
            c2v = __ldg(sv_v + sb2); c2g = __ldg(hh + sb2);
            c2d = __ldg(dvv  + sb2); c2y = __ldg(svY + sb2);
        }
        asm volatile("cp.async.commit_group;");
        asm volatile("cp.async.wait_group 2;");  // tile t's group retired; t+G, t+2G in flight
        __syncwarp();

        // ---- Compute this warp's 32 rows of tile t from buffer `buf`. ----
        float v = c0v, gap = c0g, dvl = c0d, y = c0y;
        float* bY  = smem + buf * BUFELEMS;
        float* myY = bY + tid * TS + 2;          // element 50 = tile index 2
        const float* myV = myY + RPB * TS;

        #pragma unroll
        for (int i = 0; i < NSTEP; ++i) {
            // s_star = s0 + max(v*Thw + v*dv/(2*sqrt(a*b)), 0)  (NaN-propagating max)
            float tt2    = v * Thw + (v * dvl) * inv_c2;
            float relu   = !(tt2 <= 0.0f) ? tt2 : 0.0f;
            float s_star = s0 + relu;

            float rv  = v * inv_v0;
            float rv2 = rv * rv;
            float rs  = __fdividef(s_star, gap);
            float a_calc = pa * (1.0f - rv2 * rv2 - rs * rs);

            float v2  = v + a_calc * DTC;
            // where(v2 <= 0, -v/DT, a_calc); 1/0.1f rounds to exactly 10.0f
            float a_t = (v2 <= 0.0f) ? (-v * 10.0f) : a_calc;

            v   = v + a_t * DTC;
            dvl = v - myV[i];
            y   = y + v * DTC;
            gap = myY[i] - y;     // last read of lv_Y slot i ...
            myY[i] = y;           // ... reuse it to stage the output in place
        }
        __syncwarp();

        // ---- Warp-private coalesced writeback: 960 contiguous floats. ----
        const size_t obase = (size_t)(t * RPB + wrow0) * NSTEP;
        const float* wO = bY + wrow0 * TS;
        #pragma unroll
        for (int k = 0; k < NSTEP; ++k) {
            int idx = k * 32 + lane;
            int row = idx / NSTEP;
            int col = idx - row * NSTEP;
            out[obase + idx] = wO[row * TS + 2 + col];
        }
        __syncwarp();   // SMEM reads done before this buffer is refilled (2 iters later)

        // ---- Rotate pipeline state. ----
        c0v = c1v; c0g = c1g; c0d = c1d; c0y = c1y;
        c1v = c2v; c1g = c2g; c1d = c2d; c1y = c2y;
        buf = (buf + 1) % NBUF;
        t  += (int)gridDim.x;
    }
}

extern "C" void kernel_launch(void* const* d_in, const int* in_sizes, int n_in,
                              void* d_out, int out_size) {
    const float* params = (const float*)d_in[0];
    const float* sv_v1  = (const float*)d_in[1];
    const float* h1     = (const float*)d_in[2];
    const float* dv1    = (const float*)d_in[3];
    const float* sv_Y1  = (const float*)d_in[4];
    const float* lvY    = (const float*)d_in[5];
    const float* lvv    = (const float*)d_in[6];
    float* out = (float*)d_out;

    cudaFuncSetAttribute(traj_kernel,
                         cudaFuncAttributeMaxDynamicSharedMemorySize,
                         (int)SMEM_BYTES);
    traj_kernel<<<GRID, RPB, SMEM_BYTES>>>(params, sv_v1, h1, dv1, sv_Y1,
                                           lvY, lvv, out);
}

// round 10
// speedup vs baseline: 1.1770x; 1.1770x over previous
#include <cuda_runtime.h>
#include <math.h>

#define NB      262144
#define TT      80
#define NSTEP   30
#define RPB     256               // rows (threads) per block
#define OUT_STRIDE 31             // 30 outputs + 1 pad (31 coprime 32 -> conflict-free)
#define DTC     0.1f
#define SMEM_BYTES (RPB * OUT_STRIDE * sizeof(float))   // 31744 B: output transpose only

__global__ __launch_bounds__(RPB, 2)
void traj_kernel(const float* __restrict__ params,
                 const float* __restrict__ sv_v,
                 const float* __restrict__ hh,
                 const float* __restrict__ dvv,
                 const float* __restrict__ svY,
                 const float* __restrict__ lvY,
                 const float* __restrict__ lvv,
                 float* __restrict__ out)
{
    extern __shared__ float sO[];        // [RPB][OUT_STRIDE]
    const int tid   = threadIdx.x;
    const int wid   = tid >> 5;
    const int lane  = tid & 31;
    const int wrow0 = wid * 32;
    const int row   = blockIdx.x * RPB + tid;

    // ---- Register-resident row loads: 8 float4 per array (elements 48..79,
    // 16B-aligned at byte 192). Fully unrolled -> lY/lV stay in registers,
    // 16 independent LDG.128 front-batched by ptxas for deep MLP. ----
    const size_t gbase = (size_t)row * TT;
    float lY[NSTEP], lV[NSTEP];
    #pragma unroll
    for (int j = 0; j < 8; ++j) {
        float4 a = __ldg(reinterpret_cast<const float4*>(lvY + gbase + 48 + 4 * j));
        float4 b = __ldg(reinterpret_cast<const float4*>(lvv + gbase + 48 + 4 * j));
        if (j == 0) {               // elements 48,49 discarded; 50,51 kept
            lY[0] = a.z; lY[1] = a.w;
            lV[0] = b.z; lV[1] = b.w;
        } else {
            lY[4*j - 2] = a.x; lY[4*j - 1] = a.y; lY[4*j] = a.z; lY[4*j + 1] = a.w;
            lV[4*j - 2] = b.x; lV[4*j - 1] = b.y; lV[4*j] = b.z; lV[4*j + 1] = b.w;
        }
    }

    // Per-row initial state at t=49.
    float v   = __ldg(sv_v + gbase + 49);
    float gap = __ldg(hh   + gbase + 49);
    float dvl = __ldg(dvv  + gbase + 49);
    float y   = __ldg(svY  + gbase + 49);

    // Params: broadcast, L1-resident.
    const float s0  = __ldg(params + 0);
    const float Thw = __ldg(params + 1);
    const float pa  = __ldg(params + 2);
    const float pb  = __ldg(params + 3);
    const float v0  = __ldg(params + 4);
    const float inv_c2 = 1.0f / (2.0f * sqrtf(pa * pb));
    const float inv_v0 = 1.0f / v0;

    float* myO = sO + tid * OUT_STRIDE;

    #pragma unroll
    for (int i = 0; i < NSTEP; ++i) {
        // s_star = s0 + max(v*Thw + v*dv/(2*sqrt(a*b)), 0)  (NaN-propagating max)
        float t      = v * Thw + (v * dvl) * inv_c2;
        float relu   = !(t <= 0.0f) ? t : 0.0f;
        float s_star = s0 + relu;

        float rv  = v * inv_v0;
        float rv2 = rv * rv;
        float rs  = __fdividef(s_star, gap);
        float a_calc = pa * (1.0f - rv2 * rv2 - rs * rs);

        float v2  = v + a_calc * DTC;
        // where(v2 <= 0, -v/DT, a_calc); 1/0.1f rounds to exactly 10.0f
        float a_t = (v2 <= 0.0f) ? (-v * 10.0f) : a_calc;

        v   = v + a_t * DTC;
        dvl = v - lV[i];
        y   = y + v * DTC;
        gap = lY[i] - y;
        myO[i] = y;               // stage for coalesced writeback (conflict-free STS)
    }

    __syncwarp();   // warp-private: only this warp's 32 rows are read back

    // ---- Warp-private coalesced writeback: this warp's 32 rows * 30 outputs
    // = 960 contiguous floats starting at (blockRow0 + wrow0) * NSTEP.
    const size_t obase = (size_t)(blockIdx.x * RPB + wrow0) * NSTEP;
    const float* wO = sO + wrow0 * OUT_STRIDE;
    #pragma unroll
    for (int k = 0; k < NSTEP; ++k) {
        int idx = k * 32 + lane;
        int r   = idx / NSTEP;
        int c   = idx - r * NSTEP;
        out[obase + idx] = wO[r * OUT_STRIDE + c];
    }
}

extern "C" void kernel_launch(void* const* d_in, const int* in_sizes, int n_in,
                              void* d_out, int out_size) {
    const float* params = (const float*)d_in[0];
    const float* sv_v1  = (const float*)d_in[1];
    const float* h1     = (const float*)d_in[2];
    const float* dv1    = (const float*)d_in[3];
    const float* sv_Y1  = (const float*)d_in[4];
    const float* lvY    = (const float*)d_in[5];
    const float* lvv    = (const float*)d_in[6];
    float* out = (float*)d_out;

    cudaFuncSetAttribute(traj_kernel,
                         cudaFuncAttributeMaxDynamicSharedMemorySize,
                         (int)SMEM_BYTES);
    traj_kernel<<<NB / RPB, RPB, SMEM_BYTES>>>(params, sv_v1, h1, dv1, sv_Y1,
                                               lvY, lvv, out);
}

// round 11
// speedup vs baseline: 1.3650x; 1.1597x over previous
#include <cuda_runtime.h>
#include <math.h>
#include <stdint.h>

#define NB      262144
#define TT      80
#define NSTEP   30
#define RPB     128               // rows (threads) per block / per tile (4 warps)
#define NTILES  (NB / RPB)        // 2048 full tiles, no remainder
#define TS      30                // stage exactly elements 50..79 (byte 200: 8B-aligned)
#define DTC     0.1f
#define GRID    456               // persistent: 3 CTAs per SM on 152-SM GB300
#define BUFELEMS (2 * RPB * TS)   // Y + V for one buffer (floats)
#define SMEM_BYTES (2 * BUFELEMS * sizeof(float))   // 61440 B

__device__ __forceinline__ void cpa8(uint32_t dst, const float* src) {
    asm volatile("cp.async.ca.shared.global [%0], [%1], 8;" :: "r"(dst), "l"(src));
}

__global__ __launch_bounds__(RPB, 3)
void traj_kernel(const float* __restrict__ params,
                 const float* __restrict__ sv_v,
                 const float* __restrict__ hh,
                 const float* __restrict__ dvv,
                 const float* __restrict__ svY,
                 const float* __restrict__ lvY,
                 const float* __restrict__ lvv,
                 float* __restrict__ out)
{
    extern __shared__ float smem[];      // [2][{Y,V}][RPB][TS]
    const int tid   = threadIdx.x;
    const int wid   = tid >> 5;
    const int lane  = tid & 31;
    const int wrow0 = wid * 32;
    const uint32_t smem_u32 = (uint32_t)__cvta_generic_to_shared(smem);

    // Params: broadcast, L1-resident.
    const float s0  = __ldg(params + 0);
    const float Thw = __ldg(params + 1);
    const float pa  = __ldg(params + 2);
    const float pb  = __ldg(params + 3);
    const float v0  = __ldg(params + 4);
    const float inv_c2 = 1.0f / (2.0f * sqrtf(pa * pb));
    const float inv_v0 = 1.0f / v0;

    int t   = blockIdx.x;
    int buf = 0;
    float nv = 0.f, ngap = 0.f, ndvl = 0.f, ny = 0.f;

    // ---- Prologue: async-stage tile t into buffer 0, prefetch its scalars. ----
    {
        const int r0 = t * RPB;
        // Warp stages its 32 rows: 32 rows * 15 8B-chunks = 480 = 15 iters * 32 lanes.
        #pragma unroll
        for (int k = 0; k < 15; ++k) {
            int idx = k * 32 + lane;
            int row = wrow0 + idx / 15;
            int c   = idx % 15;
            size_t g = (size_t)(r0 + row) * TT + 50 + c * 2;
            uint32_t dY = smem_u32 + (uint32_t)(row * TS + c * 2) * 4u;
            cpa8(dY, lvY + g);
            cpa8(dY + (uint32_t)(RPB * TS) * 4u, lvv + g);
        }
        asm volatile("cp.async.commit_group;");
        size_t sb = (size_t)(r0 + tid) * TT + 49;
        nv   = __ldg(sv_v + sb);
        ngap = __ldg(hh   + sb);
        ndvl = __ldg(dvv  + sb);
        ny   = __ldg(svY  + sb);
    }

    while (t < NTILES) {
        const int tn = t + (int)gridDim.x;
        float v = nv, gap = ngap, dvl = ndvl, y = ny;

        if (tn < NTILES) {
            // ---- Issue next tile's loads into the other buffer. ----
            const int r0n = tn * RPB;
            const uint32_t ob = (uint32_t)((buf ^ 1) * BUFELEMS) * 4u;
            #pragma unroll
            for (int k = 0; k < 15; ++k) {
                int idx = k * 32 + lane;
                int row = wrow0 + idx / 15;
                int c   = idx % 15;
                size_t g = (size_t)(r0n + row) * TT + 50 + c * 2;
                uint32_t dY = smem_u32 + ob + (uint32_t)(row * TS + c * 2) * 4u;
                cpa8(dY, lvY + g);
                cpa8(dY + (uint32_t)(RPB * TS) * 4u, lvv + g);
            }
            asm volatile("cp.async.commit_group;");
            size_t sb = (size_t)(r0n + tid) * TT + 49;
            nv   = __ldg(sv_v + sb);
            ngap = __ldg(hh   + sb);
            ndvl = __ldg(dvv  + sb);
            ny   = __ldg(svY  + sb);
            asm volatile("cp.async.wait_group 1;");  // tile t's group done; tn in flight
        } else {
            asm volatile("cp.async.wait_group 0;");
        }
        __syncwarp();

        // ---- Compute this warp's 32 rows from buffer `buf`. ----
        float* bY  = smem + buf * BUFELEMS;
        float* myY = bY + tid * TS;              // element 50 = index 0
        const float* myV = myY + RPB * TS;

        #pragma unroll
        for (int i = 0; i < NSTEP; ++i) {
            // s_star = s0 + max(v*Thw + v*dv/(2*sqrt(a*b)), 0)  (NaN-propagating max)
            float tt     = v * Thw + (v * dvl) * inv_c2;
            float relu   = !(tt <= 0.0f) ? tt : 0.0f;
            float s_star = s0 + relu;

            float rv  = v * inv_v0;
            float rv2 = rv * rv;
            float rs  = __fdividef(s_star, gap);
            float a_calc = pa * (1.0f - rv2 * rv2 - rs * rs);

            float v2  = v + a_calc * DTC;
            // where(v2 <= 0, -v/DT, a_calc); 1/0.1f rounds to exactly 10.0f
            float a_t = (v2 <= 0.0f) ? (-v * 10.0f) : a_calc;

            v   = v + a_t * DTC;
            dvl = v - myV[i];
            y   = y + v * DTC;
            gap = myY[i] - y;     // last read of lv_Y slot i ...
            myY[i] = y;           // ... reuse it to stage the output in place
        }
        __syncwarp();

        // ---- Warp-private coalesced writeback: 960 contiguous floats.
        // wO word index = idx exactly (TS == NSTEP) -> conflict-free LDS. ----
        const size_t obase = (size_t)(t * RPB + wrow0) * NSTEP;
        const float* wO = bY + wrow0 * TS;
        #pragma unroll
        for (int k = 0; k < NSTEP; ++k) {
            int idx = k * 32 + lane;
            out[obase + idx] = wO[idx];
        }
        __syncwarp();   // SMEM reads done before this buffer is refilled

        buf ^= 1;
        t = tn;
    }
}

extern "C" void kernel_launch(void* const* d_in, const int* in_sizes, int n_in,
                              void* d_out, int out_size) {
    const float* params = (const float*)d_in[0];
    const float* sv_v1  = (const float*)d_in[1];
    const float* h1     = (const float*)d_in[2];
    const float* dv1    = (const float*)d_in[3];
    const float* sv_Y1  = (const float*)d_in[4];
    const float* lvY    = (const float*)d_in[5];
    const float* lvv    = (const float*)d_in[6];
    float* out = (float*)d_out;

    cudaFuncSetAttribute(traj_kernel,
                         cudaFuncAttributeMaxDynamicSharedMemorySize,
                         (int)SMEM_BYTES);
    traj_kernel<<<GRID, RPB, SMEM_BYTES>>>(params, sv_v1, h1, dv1, sv_Y1,
                                           lvY, lvv, out);
}